// round 1
// baseline (speedup 1.0000x reference)
#include <cuda_runtime.h>
#include <cstdint>
#include <math.h>

// ---------------------------------------------------------------------------
// WaveNet: B=4, T=32768, NM=80, RC=120, SC=240, NB=16, ND=8, NC=256
// Strategy: fp32 everywhere (accuracy), packed fma.rn.f32x2 inner loops
// (2 FMAs/instr on the FMA pipe). One fused kernel per residual block
// (GEMM1 320->240 + gated act + GEMM2 120->360 split skip/res), ping-pong
// res buffers, fused 2-layer head kernel. Weights pre-transposed to [c][o]
// and pre-duplicated to (w,w) float2 once per launch for broadcast loads.
// ---------------------------------------------------------------------------

#define T_LEN   32768
#define BN      4
#define RC_     120
#define C2_     240     // 2*RC
#define NM_     80
#define XC_     320     // RC(shift) + RC(cur) + NM
#define O2_     360     // SC + RC (combined GEMM2 outputs)
#define SC_     240
#define NB_     16
#define NC_     256
#define TT_     64      // time tile
#define NTHR    256

// ---- scratch (device globals; no allocations allowed) ----
__device__ float  g_res[2][BN * RC_ * T_LEN];       // ping-pong residual
__device__ float  g_skip[BN * SC_ * T_LEN];         // skip accumulator
__device__ float2 g_w1[NB_ * XC_ * C2_];            // [i][c<320][o<240] dup
__device__ float2 g_w2[NB_ * RC_ * O2_];            // [i][c<120][o<360] dup
__device__ float2 g_w3[SC_ * NC_];                  // head1 [c<240][o<256] dup
__device__ float2 g_w4[NC_ * NC_];                  // head2 [c<256][o<256] dup

// ---- packed f32x2 helpers ----
__device__ __forceinline__ void fma2(unsigned long long& d,
                                     unsigned long long a,
                                     unsigned long long b) {
    asm("fma.rn.f32x2 %0, %1, %2, %3;" : "=l"(d) : "l"(a), "l"(b), "l"(d));
}
__device__ __forceinline__ unsigned long long pack2(float x, float y) {
    unsigned long long r;
    asm("mov.b64 %0, {%1, %2};" : "=l"(r) : "f"(x), "f"(y));
    return r;
}
__device__ __forceinline__ float2 unpack2(unsigned long long v) {
    float2 f;
    asm("mov.b64 {%0, %1}, %2;" : "=f"(f.x), "=f"(f.y) : "l"(v));
    return f;
}

// ---------------------------------------------------------------------------
// Weight prep: transpose to [c][o], fuse {dil0, dil1, cond} and {skip, res},
// duplicate each weight into a (w,w) float2 for the f32x2 inner loop.
// ---------------------------------------------------------------------------
__global__ void prep_kernel(const float* __restrict__ cond_w,
                            const float* __restrict__ dil_w,
                            const float* __restrict__ skip_w,
                            const float* __restrict__ res_w,
                            const float* __restrict__ out_w,
                            const float* __restrict__ end_w) {
    const int stride = gridDim.x * blockDim.x;
    const int t0 = blockIdx.x * blockDim.x + threadIdx.x;

    for (int idx = t0; idx < NB_ * XC_ * C2_; idx += stride) {
        int i = idx / (XC_ * C2_);
        int r = idx % (XC_ * C2_);
        int c = r / C2_;
        int o = r % C2_;
        float w;
        if (c < RC_)            w = dil_w[((i * C2_ + o) * RC_ + c) * 2 + 0];
        else if (c < 2 * RC_)   w = dil_w[((i * C2_ + o) * RC_ + (c - RC_)) * 2 + 1];
        else                    w = cond_w[(i * C2_ + o) * NM_ + (c - 2 * RC_)];
        g_w1[idx] = make_float2(w, w);
    }
    for (int idx = t0; idx < NB_ * RC_ * O2_; idx += stride) {
        int i = idx / (RC_ * O2_);
        int r = idx % (RC_ * O2_);
        int c = r / O2_;
        int o = r % O2_;
        float w = (o < SC_) ? skip_w[(i * SC_ + o) * RC_ + c]
                            : res_w[(i * RC_ + (o - SC_)) * RC_ + c];
        g_w2[idx] = make_float2(w, w);
    }
    for (int idx = t0; idx < SC_ * NC_; idx += stride) {
        int c = idx / NC_;
        int o = idx % NC_;
        float w = out_w[o * SC_ + c];
        g_w3[idx] = make_float2(w, w);
    }
    for (int idx = t0; idx < NC_ * NC_; idx += stride) {
        int c = idx / NC_;
        int o = idx % NC_;
        float w = end_w[o * NC_ + c];
        g_w4[idx] = make_float2(w, w);
    }
}

// ---------------------------------------------------------------------------
// Init: res0 = wav_w * wav + wav_b (1->120 channels), skip = 0
// ---------------------------------------------------------------------------
__global__ void init_kernel(const float* __restrict__ wav,
                            const float* __restrict__ wav_w,
                            const float* __restrict__ wav_b) {
    const int stride = gridDim.x * blockDim.x;
    const int t0 = blockIdx.x * blockDim.x + threadIdx.x;

    for (int idx = t0; idx < BN * RC_ * T_LEN; idx += stride) {
        int b = idx / (RC_ * T_LEN);
        int r = idx % (RC_ * T_LEN);
        int c = r >> 15;
        int t = r & (T_LEN - 1);
        g_res[0][idx] = wav_w[c] * wav[b * T_LEN + t] + wav_b[c];
    }
    for (int idx = t0; idx < BN * SC_ * T_LEN; idx += stride) {
        g_skip[idx] = 0.0f;
    }
}

// ---------------------------------------------------------------------------
// Fused residual block:
//   GEMM1: g[240][TT] = W1[240][320] @ X[320][TT]  (X = [res_shift; res; cond])
//   act[120][TT] = tanh(g[:120]) * sigmoid(g[120:])
//   GEMM2: y[360][TT] = W2[360][120] @ act ; skip += y[:240]; res' = y[240:]+res
// Thread map: og = tid/32 (output group), tp = tid%32 (time pair, 2 t each).
// SMEM: xs[320*64] floats, then 15360-float scratch (W chunk / g buffer).
// ---------------------------------------------------------------------------
__global__ __launch_bounds__(NTHR, 1) void block_kernel(
    int blk, int d, int pp,
    const float* __restrict__ cond,
    const float* __restrict__ dil_b, const float* __restrict__ cond_b,
    const float* __restrict__ skip_b, const float* __restrict__ res_b) {
    extern __shared__ float sm[];
    float* xs     = sm;                 // XC_*TT_ = 20480 floats
    float* w_area = sm + XC_ * TT_;     // 15360 floats

    const float* resin  = g_res[pp];
    float*       resout = g_res[pp ^ 1];

    const int tid = threadIdx.x;
    const int b   = blockIdx.y;
    const int t0  = blockIdx.x * TT_;

    // ---- Phase A: load X tile ----
    const float* resb  = resin + b * RC_ * T_LEN;
    const float* condb = cond + b * NM_ * T_LEN;
    for (int idx = tid; idx < XC_ * TT_; idx += NTHR) {
        int r = idx >> 6;
        int t = idx & 63;
        float v;
        if (r < RC_) {
            int tt = t0 + t - d;
            v = (tt >= 0) ? resb[(r << 15) + tt] : 0.0f;
        } else if (r < 2 * RC_) {
            v = resb[((r - RC_) << 15) + t0 + t];
        } else {
            v = condb[((r - 2 * RC_) << 15) + t0 + t];
        }
        xs[idx] = v;
    }
    __syncthreads();

    const int og = tid >> 5;
    const int tp = tid & 31;

    // ---- Phase B: GEMM1 (320 -> 240), 10 input chunks of 32 ----
    unsigned long long acc[30];
#pragma unroll
    for (int k = 0; k < 30; k++) {
        int o = og * 30 + k;
        float bv = dil_b[blk * C2_ + o] + cond_b[blk * C2_ + o];
        acc[k] = pack2(bv, bv);
    }
    const float2* w1base = g_w1 + blk * XC_ * C2_;
    for (int ch = 0; ch < 10; ch++) {
        const float2* src = w1base + ch * 32 * C2_;
        float2* wsm = (float2*)w_area;
        for (int idx = tid; idx < 32 * C2_; idx += NTHR) wsm[idx] = src[idx];
        __syncthreads();
        const unsigned long long* wsu = (const unsigned long long*)w_area;
#pragma unroll
        for (int cc = 0; cc < 32; cc++) {
            unsigned long long x2 =
                *(const unsigned long long*)(xs + ((ch * 32 + cc) << 6) + (tp << 1));
            const ulonglong2* wrow =
                (const ulonglong2*)(wsu + cc * C2_ + og * 30);
#pragma unroll
            for (int kk = 0; kk < 15; kk++) {
                ulonglong2 wv = wrow[kk];
                fma2(acc[2 * kk],     wv.x, x2);
                fma2(acc[2 * kk + 1], wv.y, x2);
            }
        }
        __syncthreads();
    }

    // ---- store g into scratch, gated activation into xs[0:120] ----
#pragma unroll
    for (int k = 0; k < 30; k++) {
        int o = og * 30 + k;
        *(unsigned long long*)(w_area + (o << 6) + (tp << 1)) = acc[k];
    }
    __syncthreads();
    for (int idx = tid; idx < RC_ * TT_; idx += NTHR) {
        int r = idx >> 6;
        int t = idx & 63;
        float gt = w_area[(r << 6) + t];
        float gs = w_area[((r + RC_) << 6) + t];
        float a = tanhf(gt);
        float s = 1.0f / (1.0f + expf(-gs));
        xs[(r << 6) + t] = a * s;
    }
    __syncthreads();

    // ---- Phase C: GEMM2 (120 -> 360), 6 input chunks of 20 ----
    unsigned long long acc2[45];
#pragma unroll
    for (int k = 0; k < 45; k++) {
        int o = og * 45 + k;
        float bv = (o < SC_) ? skip_b[blk * SC_ + o] : res_b[blk * RC_ + (o - SC_)];
        acc2[k] = pack2(bv, bv);
    }
    const float2* w2base = g_w2 + blk * RC_ * O2_;
    for (int ch = 0; ch < 6; ch++) {
        const float2* src = w2base + ch * 20 * O2_;
        float2* wsm = (float2*)w_area;
        for (int idx = tid; idx < 20 * O2_; idx += NTHR) wsm[idx] = src[idx];
        __syncthreads();
        const unsigned long long* wsu = (const unsigned long long*)w_area;
#pragma unroll
        for (int cc = 0; cc < 20; cc++) {
            unsigned long long x2 =
                *(const unsigned long long*)(xs + ((ch * 20 + cc) << 6) + (tp << 1));
            const unsigned long long* wrow = wsu + cc * O2_ + og * 45;
#pragma unroll
            for (int k = 0; k < 45; k++) fma2(acc2[k], wrow[k], x2);
        }
        __syncthreads();
    }

    // ---- epilogue: skip accumulate + residual add ----
    const int t = t0 + (tp << 1);
    float* skipb = g_skip + b * SC_ * T_LEN;
    float* resoutb = resout + b * RC_ * T_LEN;
#pragma unroll
    for (int k = 0; k < 45; k++) {
        int o = og * 45 + k;
        float2 v = unpack2(acc2[k]);
        if (o < SC_) {
            float* p = skipb + (o << 15) + t;
            float2 old = *(float2*)p;
            old.x += v.x;
            old.y += v.y;
            *(float2*)p = old;
        } else {
            int r = o - SC_;
            float2 ri = *(const float2*)(resb + (r << 15) + t);
            ri.x += v.x;
            ri.y += v.y;
            *(float2*)(resoutb + (r << 15) + t) = ri;
        }
    }
}

// ---------------------------------------------------------------------------
// Head: o = out_w @ relu(skip) + out_b; end = end_w @ relu(o) + end_b
// ---------------------------------------------------------------------------
__global__ __launch_bounds__(NTHR, 1) void final_kernel(
    float* __restrict__ out,
    const float* __restrict__ out_b,
    const float* __restrict__ end_b) {
    extern __shared__ float sm[];
    float* xs     = sm;                  // 240*64 = 15360 floats
    float* w_area = sm + 15360;          // 16384 floats
    float* os     = sm + 15360 + 16384;  // 256*64 = 16384 floats

    const int tid = threadIdx.x;
    const int b   = blockIdx.y;
    const int t0  = blockIdx.x * TT_;

    const float* skipb = g_skip + b * SC_ * T_LEN;
    for (int idx = tid; idx < SC_ * TT_; idx += NTHR) {
        int r = idx >> 6;
        int t = idx & 63;
        xs[idx] = fmaxf(skipb[(r << 15) + t0 + t], 0.0f);
    }
    __syncthreads();

    const int og = tid >> 5;
    const int tp = tid & 31;

    // ---- GEMM A: 240 -> 256, 8 chunks of 30 ----
    unsigned long long acc[32];
#pragma unroll
    for (int k = 0; k < 32; k++) {
        float bv = out_b[og * 32 + k];
        acc[k] = pack2(bv, bv);
    }
    for (int ch = 0; ch < 8; ch++) {
        const float2* src = g_w3 + ch * 30 * NC_;
        float2* wsm = (float2*)w_area;
        for (int idx = tid; idx < 30 * NC_; idx += NTHR) wsm[idx] = src[idx];
        __syncthreads();
        const unsigned long long* wsu = (const unsigned long long*)w_area;
#pragma unroll
        for (int cc = 0; cc < 30; cc++) {
            unsigned long long x2 =
                *(const unsigned long long*)(xs + ((ch * 30 + cc) << 6) + (tp << 1));
            const ulonglong2* wrow = (const ulonglong2*)(wsu + cc * NC_ + og * 32);
#pragma unroll
            for (int kk = 0; kk < 16; kk++) {
                ulonglong2 wv = wrow[kk];
                fma2(acc[2 * kk],     wv.x, x2);
                fma2(acc[2 * kk + 1], wv.y, x2);
            }
        }
        __syncthreads();
    }
    // relu -> os
#pragma unroll
    for (int k = 0; k < 32; k++) {
        int o = og * 32 + k;
        float2 v = unpack2(acc[k]);
        v.x = fmaxf(v.x, 0.0f);
        v.y = fmaxf(v.y, 0.0f);
        *(float2*)(os + (o << 6) + (tp << 1)) = v;
    }
    __syncthreads();

    // ---- GEMM B: 256 -> 256, 8 chunks of 32 ----
#pragma unroll
    for (int k = 0; k < 32; k++) {
        float bv = end_b[og * 32 + k];
        acc[k] = pack2(bv, bv);
    }
    for (int ch = 0; ch < 8; ch++) {
        const float2* src = g_w4 + ch * 32 * NC_;
        float2* wsm = (float2*)w_area;
        for (int idx = tid; idx < 32 * NC_; idx += NTHR) wsm[idx] = src[idx];
        __syncthreads();
        const unsigned long long* wsu = (const unsigned long long*)w_area;
#pragma unroll
        for (int cc = 0; cc < 32; cc++) {
            unsigned long long x2 =
                *(const unsigned long long*)(os + ((ch * 32 + cc) << 6) + (tp << 1));
            const ulonglong2* wrow = (const ulonglong2*)(wsu + cc * NC_ + og * 32);
#pragma unroll
            for (int kk = 0; kk < 16; kk++) {
                ulonglong2 wv = wrow[kk];
                fma2(acc[2 * kk],     wv.x, x2);
                fma2(acc[2 * kk + 1], wv.y, x2);
            }
        }
        __syncthreads();
    }

    float* outb = out + b * NC_ * T_LEN;
    const int t = t0 + (tp << 1);
#pragma unroll
    for (int k = 0; k < 32; k++) {
        int o = og * 32 + k;
        *(float2*)(outb + (o << 15) + t) = unpack2(acc[k]);
    }
}

// ---------------------------------------------------------------------------
extern "C" void kernel_launch(void* const* d_in, const int* in_sizes, int n_in,
                              void* d_out, int out_size) {
    const float* wav    = (const float*)d_in[0];
    const float* cond   = (const float*)d_in[1];
    const float* wav_w  = (const float*)d_in[2];
    const float* wav_b  = (const float*)d_in[3];
    const float* cond_w = (const float*)d_in[4];
    const float* cond_b = (const float*)d_in[5];
    const float* dil_w  = (const float*)d_in[6];
    const float* dil_b  = (const float*)d_in[7];
    const float* skip_w = (const float*)d_in[8];
    const float* skip_b = (const float*)d_in[9];
    const float* res_w  = (const float*)d_in[10];
    const float* res_b  = (const float*)d_in[11];
    const float* out_w  = (const float*)d_in[12];
    const float* out_b  = (const float*)d_in[13];
    const float* end_w  = (const float*)d_in[14];
    const float* end_b  = (const float*)d_in[15];
    float* out = (float*)d_out;

    const int SMEM_BLK = (XC_ * TT_ + 15360) * (int)sizeof(float);        // 143360
    const int SMEM_FIN = (15360 + 16384 + 16384) * (int)sizeof(float);    // 192512
    cudaFuncSetAttribute(block_kernel, cudaFuncAttributeMaxDynamicSharedMemorySize, SMEM_BLK);
    cudaFuncSetAttribute(final_kernel, cudaFuncAttributeMaxDynamicSharedMemorySize, SMEM_FIN);

    prep_kernel<<<256, 256>>>(cond_w, dil_w, skip_w, res_w, out_w, end_w);
    init_kernel<<<592, 256>>>(wav, wav_w, wav_b);

    dim3 grid(T_LEN / TT_, BN);
    for (int i = 0; i < NB_; i++) {
        int d = 1 << (i & 7);
        block_kernel<<<grid, NTHR, SMEM_BLK>>>(i, d, i & 1, cond,
                                               dil_b, cond_b, skip_b, res_b);
    }
    final_kernel<<<grid, NTHR, SMEM_FIN>>>(out, out_b, end_b);
}

// round 2
// speedup vs baseline: 2.9918x; 2.9918x over previous
#include <cuda_runtime.h>
#include <cstdint>
#include <math.h>

// ---------------------------------------------------------------------------
// WaveNet B=4 T=32768 RC=120 SC=240 NB=16 NC=256.
// R2: register-tiled f32x2 GEMMs. f32x2 packs OUTPUT pairs (o, o+1), so
// weights stay non-duplicated [c][o] (natural float2); x is dup'd on the fly
// with one mov.b64. Thread tile: 8out x 4t (GEMM1), 12out x 4t (GEMM2),
// 512 threads/CTA (16 warps). Single fused kernel per residual block.
// ---------------------------------------------------------------------------

#define T_LEN   32768
#define BN      4
#define RC_     120
#define C2_     240
#define NM_     80
#define XC_     320
#define O2_     360
#define SC_     240
#define NB_     16
#define NC_     256
#define TT_     64
#define NTHR    512

// ---- device-global scratch ----
__device__ float g_res[2][BN * RC_ * T_LEN];
__device__ float g_skip[BN * SC_ * T_LEN];
__device__ float g_w1[NB_ * XC_ * C2_];   // [i][c<320][o<240]
__device__ float g_w2[NB_ * RC_ * O2_];   // [i][c<120][o<360]
__device__ float g_w3[SC_ * NC_];         // [c<240][o<256]
__device__ float g_w4[NC_ * NC_];         // [c<256][o<256]

// ---- f32x2 helpers ----
__device__ __forceinline__ void fma2(unsigned long long& d,
                                     unsigned long long a,
                                     unsigned long long b) {
    asm("fma.rn.f32x2 %0, %1, %2, %3;" : "=l"(d) : "l"(a), "l"(b), "l"(d));
}
__device__ __forceinline__ unsigned long long pack2(float x, float y) {
    unsigned long long r;
    asm("mov.b64 %0, {%1, %2};" : "=l"(r) : "f"(x), "f"(y));
    return r;
}
__device__ __forceinline__ float2 unpack2(unsigned long long v) {
    float2 f;
    asm("mov.b64 {%0, %1}, %2;" : "=f"(f.x), "=f"(f.y) : "l"(v));
    return f;
}

// ---------------------------------------------------------------------------
__global__ void prep_kernel(const float* __restrict__ cond_w,
                            const float* __restrict__ dil_w,
                            const float* __restrict__ skip_w,
                            const float* __restrict__ res_w,
                            const float* __restrict__ out_w,
                            const float* __restrict__ end_w) {
    const int stride = gridDim.x * blockDim.x;
    const int t0 = blockIdx.x * blockDim.x + threadIdx.x;

    for (int idx = t0; idx < NB_ * XC_ * C2_; idx += stride) {
        int i = idx / (XC_ * C2_);
        int r = idx % (XC_ * C2_);
        int c = r / C2_;
        int o = r % C2_;
        float w;
        if (c < RC_)          w = dil_w[((i * C2_ + o) * RC_ + c) * 2 + 0];
        else if (c < 2 * RC_) w = dil_w[((i * C2_ + o) * RC_ + (c - RC_)) * 2 + 1];
        else                  w = cond_w[(i * C2_ + o) * NM_ + (c - 2 * RC_)];
        g_w1[idx] = w;
    }
    for (int idx = t0; idx < NB_ * RC_ * O2_; idx += stride) {
        int i = idx / (RC_ * O2_);
        int r = idx % (RC_ * O2_);
        int c = r / O2_;
        int o = r % O2_;
        g_w2[idx] = (o < SC_) ? skip_w[(i * SC_ + o) * RC_ + c]
                              : res_w[(i * RC_ + (o - SC_)) * RC_ + c];
    }
    for (int idx = t0; idx < SC_ * NC_; idx += stride) {
        int c = idx / NC_;
        int o = idx % NC_;
        g_w3[idx] = out_w[o * SC_ + c];
    }
    for (int idx = t0; idx < NC_ * NC_; idx += stride) {
        int c = idx / NC_;
        int o = idx % NC_;
        g_w4[idx] = end_w[o * NC_ + c];
    }
}

__global__ void init_kernel(const float* __restrict__ wav,
                            const float* __restrict__ wav_w,
                            const float* __restrict__ wav_b) {
    const int stride = gridDim.x * blockDim.x;
    const int t0 = blockIdx.x * blockDim.x + threadIdx.x;
    for (int idx = t0; idx < BN * RC_ * T_LEN; idx += stride) {
        int b = idx / (RC_ * T_LEN);
        int r = idx % (RC_ * T_LEN);
        int c = r >> 15;
        int t = r & (T_LEN - 1);
        g_res[0][idx] = wav_w[c] * wav[b * T_LEN + t] + wav_b[c];
    }
    for (int idx = t0; idx < BN * SC_ * T_LEN; idx += stride)
        g_skip[idx] = 0.0f;
}

// ---------------------------------------------------------------------------
// Fused residual block.
// SMEM layout (floats):
//   GEMM1: xs[320*64] @0 (81920B) | wbuf[80*240] @20480 (76800B)
//          g stored into wbuf region as [120 opairs][64 t][2]
//   GEMM2: act[120*64] @0 (30720B) | w2s[120*360] @7680 (172800B)
// total = 203520 B
// ---------------------------------------------------------------------------
__global__ __launch_bounds__(NTHR, 1) void block_kernel(
    int blk, int d, int pp,
    const float* __restrict__ cond,
    const float* __restrict__ dil_b, const float* __restrict__ cond_b,
    const float* __restrict__ skip_b, const float* __restrict__ res_b) {
    extern __shared__ float sm[];
    float* xs   = sm;
    float* wbuf = sm + XC_ * TT_;       // 20480
    float* gbuf = wbuf;
    float* act  = sm;
    float* w2s  = sm + RC_ * TT_;       // 7680

    const int tid = threadIdx.x;
    const int b   = blockIdx.y;
    const int t0  = blockIdx.x * TT_;

    const float* resin  = g_res[pp] + b * RC_ * T_LEN;
    float*       resout = g_res[pp ^ 1] + b * RC_ * T_LEN;
    const float* condb  = cond + b * NM_ * T_LEN;

    // ---- stage X tile: [res_shift(120); res(120); cond(80)] x 64t ----
    for (int idx = tid; idx < XC_ * TT_; idx += NTHR) {
        int r = idx >> 6;
        int t = idx & 63;
        float v;
        if (r < RC_) {
            int tt = t0 + t - d;
            v = (tt >= 0) ? resin[(r << 15) + tt] : 0.0f;
        } else if (r < 2 * RC_) {
            v = resin[((r - RC_) << 15) + t0 + t];
        } else {
            v = condb[((r - 2 * RC_) << 15) + t0 + t];
        }
        xs[idx] = v;
    }

    const int og = tid >> 4;       // 0..31 (30 active)
    const int tg = tid & 15;       // time group (4 t each)
    const bool active = (og < 30);

    // ---- GEMM1: 240 outs x 64 t, K=320 in 4 chunks of 80 ----
    unsigned long long acc[4][4];
    if (active) {
#pragma unroll
        for (int p = 0; p < 4; p++) {
            int o = og * 8 + p * 2;
            float b0 = dil_b[blk * C2_ + o]     + cond_b[blk * C2_ + o];
            float b1 = dil_b[blk * C2_ + o + 1] + cond_b[blk * C2_ + o + 1];
            unsigned long long bv = pack2(b0, b1);
#pragma unroll
            for (int j = 0; j < 4; j++) acc[p][j] = bv;
        }
    }

    const float* w1base = g_w1 + blk * XC_ * C2_;
    for (int ch = 0; ch < 4; ch++) {
        __syncthreads();
        {
            const float4* src = (const float4*)(w1base + ch * 80 * C2_);
            float4* dst = (float4*)wbuf;
            for (int idx = tid; idx < 80 * C2_ / 4; idx += NTHR) dst[idx] = src[idx];
        }
        __syncthreads();
        if (active) {
#pragma unroll 4
            for (int cc = 0; cc < 80; cc++) {
                float4 xv = *(const float4*)(xs + ((ch * 80 + cc) << 6) + (tg << 2));
                unsigned long long xx0 = pack2(xv.x, xv.x);
                unsigned long long xx1 = pack2(xv.y, xv.y);
                unsigned long long xx2 = pack2(xv.z, xv.z);
                unsigned long long xx3 = pack2(xv.w, xv.w);
                const ulonglong2* wrow = (const ulonglong2*)(wbuf + cc * C2_ + og * 8);
                ulonglong2 wA = wrow[0];   // pairs 0,1
                ulonglong2 wB = wrow[1];   // pairs 2,3
                fma2(acc[0][0], wA.x, xx0); fma2(acc[0][1], wA.x, xx1);
                fma2(acc[0][2], wA.x, xx2); fma2(acc[0][3], wA.x, xx3);
                fma2(acc[1][0], wA.y, xx0); fma2(acc[1][1], wA.y, xx1);
                fma2(acc[1][2], wA.y, xx2); fma2(acc[1][3], wA.y, xx3);
                fma2(acc[2][0], wB.x, xx0); fma2(acc[2][1], wB.x, xx1);
                fma2(acc[2][2], wB.x, xx2); fma2(acc[2][3], wB.x, xx3);
                fma2(acc[3][0], wB.y, xx0); fma2(acc[3][1], wB.y, xx1);
                fma2(acc[3][2], wB.y, xx2); fma2(acc[3][3], wB.y, xx3);
            }
        }
    }

    // ---- store g into gbuf as [opair][t][2], then gated activation ----
    __syncthreads();
    if (active) {
#pragma unroll
        for (int p = 0; p < 4; p++)
#pragma unroll
            for (int j = 0; j < 4; j++) {
                int opair = og * 4 + p;
                int t = tg * 4 + j;
                *(unsigned long long*)(gbuf + opair * 128 + t * 2) = acc[p][j];
            }
    }
    __syncthreads();
    for (int idx = tid; idx < RC_ * TT_; idx += NTHR) {
        int o = idx >> 6;
        int t = idx & 63;
        float gt = gbuf[(o >> 1) * 128 + t * 2 + (o & 1)];
        float gs = gbuf[((o >> 1) + 60) * 128 + t * 2 + (o & 1)];
        float a = tanhf(gt);
        float s = 1.0f / (1.0f + expf(-gs));
        act[o * 64 + t] = a * s;          // overwrites dead xs rows 0..119
    }
    __syncthreads();

    // ---- stage full W2 (120x360) ----
    {
        const float4* src = (const float4*)(g_w2 + blk * RC_ * O2_);
        float4* dst = (float4*)w2s;
        for (int idx = tid; idx < RC_ * O2_ / 4; idx += NTHR) dst[idx] = src[idx];
    }
    __syncthreads();

    // ---- GEMM2: 360 outs x 64 t, K=120 ----
    unsigned long long acc2[6][4];
    if (active) {
#pragma unroll
        for (int q = 0; q < 6; q++) {
            int o = og * 12 + q * 2;
            float b0 = (o < SC_)     ? skip_b[blk * SC_ + o]     : res_b[blk * RC_ + o - SC_];
            float b1 = (o + 1 < SC_) ? skip_b[blk * SC_ + o + 1] : res_b[blk * RC_ + o + 1 - SC_];
            unsigned long long bv = pack2(b0, b1);
#pragma unroll
            for (int j = 0; j < 4; j++) acc2[q][j] = bv;
        }
#pragma unroll 4
        for (int cc = 0; cc < RC_; cc++) {
            float4 xv = *(const float4*)(act + (cc << 6) + (tg << 2));
            unsigned long long xx0 = pack2(xv.x, xv.x);
            unsigned long long xx1 = pack2(xv.y, xv.y);
            unsigned long long xx2 = pack2(xv.z, xv.z);
            unsigned long long xx3 = pack2(xv.w, xv.w);
            const ulonglong2* wrow = (const ulonglong2*)(w2s + cc * O2_ + og * 12);
            ulonglong2 wA = wrow[0];
            ulonglong2 wB = wrow[1];
            ulonglong2 wC = wrow[2];
            fma2(acc2[0][0], wA.x, xx0); fma2(acc2[0][1], wA.x, xx1);
            fma2(acc2[0][2], wA.x, xx2); fma2(acc2[0][3], wA.x, xx3);
            fma2(acc2[1][0], wA.y, xx0); fma2(acc2[1][1], wA.y, xx1);
            fma2(acc2[1][2], wA.y, xx2); fma2(acc2[1][3], wA.y, xx3);
            fma2(acc2[2][0], wB.x, xx0); fma2(acc2[2][1], wB.x, xx1);
            fma2(acc2[2][2], wB.x, xx2); fma2(acc2[2][3], wB.x, xx3);
            fma2(acc2[3][0], wB.y, xx0); fma2(acc2[3][1], wB.y, xx1);
            fma2(acc2[3][2], wB.y, xx2); fma2(acc2[3][3], wB.y, xx3);
            fma2(acc2[4][0], wC.x, xx0); fma2(acc2[4][1], wC.x, xx1);
            fma2(acc2[4][2], wC.x, xx2); fma2(acc2[4][3], wC.x, xx3);
            fma2(acc2[5][0], wC.y, xx0); fma2(acc2[5][1], wC.y, xx1);
            fma2(acc2[5][2], wC.y, xx2); fma2(acc2[5][3], wC.y, xx3);
        }
    }

    // ---- epilogue: skip += / res' = res + y ----
    if (active) {
        const int t = t0 + (tg << 2);
        float* skipb = g_skip + b * SC_ * T_LEN;
#pragma unroll
        for (int q = 0; q < 6; q++) {
            float2 v0 = unpack2(acc2[q][0]);
            float2 v1 = unpack2(acc2[q][1]);
            float2 v2 = unpack2(acc2[q][2]);
            float2 v3 = unpack2(acc2[q][3]);
            int o = og * 12 + q * 2;
            if (o < SC_) {
                float4* p0 = (float4*)(skipb + (o << 15) + t);
                float4* p1 = (float4*)(skipb + ((o + 1) << 15) + t);
                float4 c0 = *p0, c1 = *p1;
                c0.x += v0.x; c0.y += v1.x; c0.z += v2.x; c0.w += v3.x;
                c1.x += v0.y; c1.y += v1.y; c1.z += v2.y; c1.w += v3.y;
                *p0 = c0; *p1 = c1;
            } else {
                int r = o - SC_;
                float4 r0 = *(const float4*)(resin + (r << 15) + t);
                float4 r1 = *(const float4*)(resin + ((r + 1) << 15) + t);
                r0.x += v0.x; r0.y += v1.x; r0.z += v2.x; r0.w += v3.x;
                r1.x += v0.y; r1.y += v1.y; r1.z += v2.y; r1.w += v3.y;
                *(float4*)(resout + (r << 15) + t) = r0;
                *(float4*)(resout + ((r + 1) << 15) + t) = r1;
            }
        }
    }
}

// ---------------------------------------------------------------------------
// Head: o = relu(out_w@relu(skip)+out_b); end = end_w@o + end_b
// SMEM: GEMM A: xs[240*64] @0 (61440B) | wbufA[120*256] @15360 (122880B)
//       GEMM B: oact[256*64] @0 (65536B) | wbufB[128*256] @16384 (131072B)
// total = 196608 B
// ---------------------------------------------------------------------------
__global__ __launch_bounds__(NTHR, 1) void final_kernel(
    float* __restrict__ out,
    const float* __restrict__ out_b,
    const float* __restrict__ end_b) {
    extern __shared__ float sm[];
    float* xs    = sm;
    float* wbufA = sm + SC_ * TT_;      // 15360
    float* oact  = sm;
    float* wbufB = sm + NC_ * TT_;      // 16384

    const int tid = threadIdx.x;
    const int b   = blockIdx.y;
    const int t0  = blockIdx.x * TT_;

    const float* skipb = g_skip + b * SC_ * T_LEN;
    for (int idx = tid; idx < SC_ * TT_; idx += NTHR) {
        int r = idx >> 6;
        int t = idx & 63;
        xs[idx] = fmaxf(skipb[(r << 15) + t0 + t], 0.0f);
    }

    const int og = tid >> 4;    // 0..31, all active
    const int tg = tid & 15;

    // ---- GEMM A: 256 outs, K=240 in 2 chunks of 120 ----
    unsigned long long acc[4][4];
#pragma unroll
    for (int p = 0; p < 4; p++) {
        int o = og * 8 + p * 2;
        unsigned long long bv = pack2(out_b[o], out_b[o + 1]);
#pragma unroll
        for (int j = 0; j < 4; j++) acc[p][j] = bv;
    }
    for (int ch = 0; ch < 2; ch++) {
        __syncthreads();
        {
            const float4* src = (const float4*)(g_w3 + ch * 120 * NC_);
            float4* dst = (float4*)wbufA;
            for (int idx = tid; idx < 120 * NC_ / 4; idx += NTHR) dst[idx] = src[idx];
        }
        __syncthreads();
#pragma unroll 4
        for (int cc = 0; cc < 120; cc++) {
            float4 xv = *(const float4*)(xs + ((ch * 120 + cc) << 6) + (tg << 2));
            unsigned long long xx0 = pack2(xv.x, xv.x);
            unsigned long long xx1 = pack2(xv.y, xv.y);
            unsigned long long xx2 = pack2(xv.z, xv.z);
            unsigned long long xx3 = pack2(xv.w, xv.w);
            const ulonglong2* wrow = (const ulonglong2*)(wbufA + cc * NC_ + og * 8);
            ulonglong2 wA = wrow[0];
            ulonglong2 wB = wrow[1];
            fma2(acc[0][0], wA.x, xx0); fma2(acc[0][1], wA.x, xx1);
            fma2(acc[0][2], wA.x, xx2); fma2(acc[0][3], wA.x, xx3);
            fma2(acc[1][0], wA.y, xx0); fma2(acc[1][1], wA.y, xx1);
            fma2(acc[1][2], wA.y, xx2); fma2(acc[1][3], wA.y, xx3);
            fma2(acc[2][0], wB.x, xx0); fma2(acc[2][1], wB.x, xx1);
            fma2(acc[2][2], wB.x, xx2); fma2(acc[2][3], wB.x, xx3);
            fma2(acc[3][0], wB.y, xx0); fma2(acc[3][1], wB.y, xx1);
            fma2(acc[3][2], wB.y, xx2); fma2(acc[3][3], wB.y, xx3);
        }
    }

    // ---- relu -> oact [o][t] ----
    __syncthreads();
#pragma unroll
    for (int p = 0; p < 4; p++) {
        float2 v0 = unpack2(acc[p][0]);
        float2 v1 = unpack2(acc[p][1]);
        float2 v2 = unpack2(acc[p][2]);
        float2 v3 = unpack2(acc[p][3]);
        int o = og * 8 + p * 2;
        float4 r0 = make_float4(fmaxf(v0.x, 0.f), fmaxf(v1.x, 0.f),
                                fmaxf(v2.x, 0.f), fmaxf(v3.x, 0.f));
        float4 r1 = make_float4(fmaxf(v0.y, 0.f), fmaxf(v1.y, 0.f),
                                fmaxf(v2.y, 0.f), fmaxf(v3.y, 0.f));
        *(float4*)(oact + (o << 6) + (tg << 2)) = r0;
        *(float4*)(oact + ((o + 1) << 6) + (tg << 2)) = r1;
    }

    // ---- GEMM B: 256 outs, K=256 in 2 chunks of 128 ----
    unsigned long long acc2[4][4];
#pragma unroll
    for (int p = 0; p < 4; p++) {
        int o = og * 8 + p * 2;
        unsigned long long bv = pack2(end_b[o], end_b[o + 1]);
#pragma unroll
        for (int j = 0; j < 4; j++) acc2[p][j] = bv;
    }
    for (int ch = 0; ch < 2; ch++) {
        __syncthreads();
        {
            const float4* src = (const float4*)(g_w4 + ch * 128 * NC_);
            float4* dst = (float4*)wbufB;
            for (int idx = tid; idx < 128 * NC_ / 4; idx += NTHR) dst[idx] = src[idx];
        }
        __syncthreads();
#pragma unroll 4
        for (int cc = 0; cc < 128; cc++) {
            float4 xv = *(const float4*)(oact + ((ch * 128 + cc) << 6) + (tg << 2));
            unsigned long long xx0 = pack2(xv.x, xv.x);
            unsigned long long xx1 = pack2(xv.y, xv.y);
            unsigned long long xx2 = pack2(xv.z, xv.z);
            unsigned long long xx3 = pack2(xv.w, xv.w);
            const ulonglong2* wrow = (const ulonglong2*)(wbufB + cc * NC_ + og * 8);
            ulonglong2 wA = wrow[0];
            ulonglong2 wB = wrow[1];
            fma2(acc2[0][0], wA.x, xx0); fma2(acc2[0][1], wA.x, xx1);
            fma2(acc2[0][2], wA.x, xx2); fma2(acc2[0][3], wA.x, xx3);
            fma2(acc2[1][0], wA.y, xx0); fma2(acc2[1][1], wA.y, xx1);
            fma2(acc2[1][2], wA.y, xx2); fma2(acc2[1][3], wA.y, xx3);
            fma2(acc2[2][0], wB.x, xx0); fma2(acc2[2][1], wB.x, xx1);
            fma2(acc2[2][2], wB.x, xx2); fma2(acc2[2][3], wB.x, xx3);
            fma2(acc2[3][0], wB.y, xx0); fma2(acc2[3][1], wB.y, xx1);
            fma2(acc2[3][2], wB.y, xx2); fma2(acc2[3][3], wB.y, xx3);
        }
    }

    // ---- write end ----
    float* outb = out + b * NC_ * T_LEN;
    const int t = t0 + (tg << 2);
#pragma unroll
    for (int p = 0; p < 4; p++) {
        float2 v0 = unpack2(acc2[p][0]);
        float2 v1 = unpack2(acc2[p][1]);
        float2 v2 = unpack2(acc2[p][2]);
        float2 v3 = unpack2(acc2[p][3]);
        int o = og * 8 + p * 2;
        *(float4*)(outb + (o << 15) + t) = make_float4(v0.x, v1.x, v2.x, v3.x);
        *(float4*)(outb + ((o + 1) << 15) + t) = make_float4(v0.y, v1.y, v2.y, v3.y);
    }
}

// ---------------------------------------------------------------------------
extern "C" void kernel_launch(void* const* d_in, const int* in_sizes, int n_in,
                              void* d_out, int out_size) {
    const float* wav    = (const float*)d_in[0];
    const float* cond   = (const float*)d_in[1];
    const float* wav_w  = (const float*)d_in[2];
    const float* wav_b  = (const float*)d_in[3];
    const float* cond_w = (const float*)d_in[4];
    const float* cond_b = (const float*)d_in[5];
    const float* dil_w  = (const float*)d_in[6];
    const float* dil_b  = (const float*)d_in[7];
    const float* skip_w = (const float*)d_in[8];
    const float* skip_b = (const float*)d_in[9];
    const float* res_w  = (const float*)d_in[10];
    const float* res_b  = (const float*)d_in[11];
    const float* out_w  = (const float*)d_in[12];
    const float* out_b  = (const float*)d_in[13];
    const float* end_w  = (const float*)d_in[14];
    const float* end_b  = (const float*)d_in[15];
    float* out = (float*)d_out;

    const int SMEM_BLK = (RC_ * TT_ + RC_ * O2_) * (int)sizeof(float);    // 203520
    const int SMEM_FIN = (NC_ * TT_ + 128 * NC_) * (int)sizeof(float);    // 196608
    cudaFuncSetAttribute(block_kernel, cudaFuncAttributeMaxDynamicSharedMemorySize, SMEM_BLK);
    cudaFuncSetAttribute(final_kernel, cudaFuncAttributeMaxDynamicSharedMemorySize, SMEM_FIN);

    prep_kernel<<<256, 256>>>(cond_w, dil_w, skip_w, res_w, out_w, end_w);
    init_kernel<<<592, 256>>>(wav, wav_w, wav_b);

    dim3 grid(T_LEN / TT_, BN);
    for (int i = 0; i < NB_; i++) {
        int d = 1 << (i & 7);
        block_kernel<<<grid, NTHR, SMEM_BLK>>>(i, d, i & 1, cond,
                                               dil_b, cond_b, skip_b, res_b);
    }
    final_kernel<<<grid, NTHR, SMEM_FIN>>>(out, out_b, end_b);
}

// round 5
// speedup vs baseline: 3.6423x; 1.2174x over previous
#include <cuda_runtime.h>
#include <cstdint>
#include <math.h>

// ---------------------------------------------------------------------------
// WaveNet B=4 T=32768 RC=120 SC=240 NB=16 NC=256.
// R3 (second resubmit after infra timeouts): f32x2 register-tiled GEMMs +
// cp.async triple-buffered weight pipeline, in-register gated activation
// (outputs o and o+120 in same thread), fast exp-based tanh/sigmoid. One
// fused kernel per residual block.
// ---------------------------------------------------------------------------

#define T_LEN   32768
#define BN      4
#define RC_     120
#define C2_     240
#define NM_     80
#define XC_     320
#define O2_     360
#define SC_     240
#define NB_     16
#define NC_     256
#define TT_     64
#define NTHR    512

// ---- device-global scratch ----
__device__ __align__(16) float g_res[2][BN * RC_ * T_LEN];
__device__ __align__(16) float g_skip[BN * SC_ * T_LEN];
__device__ __align__(16) float g_w1[NB_ * XC_ * C2_];   // [i][c<320][o<240]
__device__ __align__(16) float g_w2[NB_ * RC_ * O2_];   // [i][c<120][o<360]
__device__ __align__(16) float g_w3[SC_ * NC_];         // [c<240][o<256]
__device__ __align__(16) float g_w4[NC_ * NC_];         // [c<256][o<256]

// ---- f32x2 helpers ----
__device__ __forceinline__ void fma2(unsigned long long& d,
                                     unsigned long long a,
                                     unsigned long long b) {
    asm("fma.rn.f32x2 %0, %1, %2, %3;" : "=l"(d) : "l"(a), "l"(b), "l"(d));
}
__device__ __forceinline__ unsigned long long pack2(float x, float y) {
    unsigned long long r;
    asm("mov.b64 %0, {%1, %2};" : "=l"(r) : "f"(x), "f"(y));
    return r;
}
__device__ __forceinline__ float2 unpack2(unsigned long long v) {
    float2 f;
    asm("mov.b64 {%0, %1}, %2;" : "=f"(f.x), "=f"(f.y) : "l"(v));
    return f;
}

// ---- cp.async helpers ----
__device__ __forceinline__ void cp16(uint32_t dst, const void* src) {
    asm volatile("cp.async.cg.shared.global [%0], [%1], 16;"
                 :: "r"(dst), "l"(src) : "memory");
}
__device__ __forceinline__ void cp_commit() {
    asm volatile("cp.async.commit_group;" ::: "memory");
}
template <int N>
__device__ __forceinline__ void cp_wait() {
    asm volatile("cp.async.wait_group %0;" :: "n"(N) : "memory");
}

// ---- fast activations (ex2/rcp.approx based; rel err ~1e-6) ----
__device__ __forceinline__ float fast_tanh(float x) {
    float e = __expf(2.0f * x);
    return 1.0f - __fdividef(2.0f, e + 1.0f);
}
__device__ __forceinline__ float fast_sig(float x) {
    return __fdividef(1.0f, 1.0f + __expf(-x));
}

// ---------------------------------------------------------------------------
__global__ void prep_kernel(const float* __restrict__ cond_w,
                            const float* __restrict__ dil_w,
                            const float* __restrict__ skip_w,
                            const float* __restrict__ res_w,
                            const float* __restrict__ out_w,
                            const float* __restrict__ end_w) {
    const int stride = gridDim.x * blockDim.x;
    const int t0 = blockIdx.x * blockDim.x + threadIdx.x;

    for (int idx = t0; idx < NB_ * XC_ * C2_; idx += stride) {
        int i = idx / (XC_ * C2_);
        int r = idx % (XC_ * C2_);
        int c = r / C2_;
        int o = r % C2_;
        float w;
        if (c < RC_)          w = dil_w[((i * C2_ + o) * RC_ + c) * 2 + 0];
        else if (c < 2 * RC_) w = dil_w[((i * C2_ + o) * RC_ + (c - RC_)) * 2 + 1];
        else                  w = cond_w[(i * C2_ + o) * NM_ + (c - 2 * RC_)];
        g_w1[idx] = w;
    }
    for (int idx = t0; idx < NB_ * RC_ * O2_; idx += stride) {
        int i = idx / (RC_ * O2_);
        int r = idx % (RC_ * O2_);
        int c = r / O2_;
        int o = r % O2_;
        g_w2[idx] = (o < SC_) ? skip_w[(i * SC_ + o) * RC_ + c]
                              : res_w[(i * RC_ + (o - SC_)) * RC_ + c];
    }
    for (int idx = t0; idx < SC_ * NC_; idx += stride) {
        int c = idx / NC_;
        int o = idx % NC_;
        g_w3[idx] = out_w[o * SC_ + c];
    }
    for (int idx = t0; idx < NC_ * NC_; idx += stride) {
        int c = idx / NC_;
        int o = idx % NC_;
        g_w4[idx] = end_w[o * NC_ + c];
    }
}

__global__ void init_kernel(const float* __restrict__ wav,
                            const float* __restrict__ wav_w,
                            const float* __restrict__ wav_b) {
    const int stride = gridDim.x * blockDim.x;
    const int t0 = blockIdx.x * blockDim.x + threadIdx.x;
    for (int idx = t0; idx < BN * RC_ * T_LEN; idx += stride) {
        int b = idx / (RC_ * T_LEN);
        int r = idx % (RC_ * T_LEN);
        int c = r >> 15;
        int t = r & (T_LEN - 1);
        g_res[0][idx] = wav_w[c] * wav[b * T_LEN + t] + wav_b[c];
    }
    for (int idx = t0; idx < BN * SC_ * T_LEN; idx += stride)
        g_skip[idx] = 0.0f;
}

// ---------------------------------------------------------------------------
// Fused residual block. SMEM (floats):
//   xs   [0, 20480)        : X tile 320 rows x 64 t            (phase 1)
//   wb_k [20480 + k*9600)  : 3 weight buffers, 40x240 each     (phase 1)
//   w2   [0, 43200)        : full W2 120x360                   (phase 2)
//   act  [43200, 50880)    : 120 x 64                          (phase 2)
// total 50880 floats = 203520 B
// ---------------------------------------------------------------------------
#define XS_F    0
#define WB_F    20480
#define WCHUNK  9600        // 40 rows * 240
#define W2_F    0
#define ACT_F   43200

__global__ __launch_bounds__(NTHR, 1) void block_kernel(
    int blk, int d, int pp,
    const float* __restrict__ cond,
    const float* __restrict__ dil_b, const float* __restrict__ cond_b,
    const float* __restrict__ skip_b, const float* __restrict__ res_b) {
    extern __shared__ float sm[];
    const uint32_t smb = (uint32_t)__cvta_generic_to_shared(sm);

    const int tid = threadIdx.x;
    const int b   = blockIdx.y;
    const int t0  = blockIdx.x * TT_;

    const float* resin  = g_res[pp] + b * RC_ * T_LEN;
    float*       resout = g_res[pp ^ 1] + b * RC_ * T_LEN;
    const float* condb  = cond + b * NM_ * T_LEN;
    const float* w1base = g_w1 + blk * XC_ * C2_;

    // ---- prologue: cp.async W1 chunks 0,1 ----
#pragma unroll 1
    for (int ch = 0; ch < 2; ch++) {
        const float* src = w1base + ch * WCHUNK;
        uint32_t dst = smb + (WB_F + ch * WCHUNK) * 4;
        for (int i = tid; i < WCHUNK / 4; i += NTHR)
            cp16(dst + i * 16, src + i * 4);
        cp_commit();
    }

    // ---- stage X tile ----
    // rows 120..319 (current res + cond): vectorized
    float* xs = sm + XS_F;
    for (int idx = tid; idx < 200 * 16; idx += NTHR) {
        int rr = idx >> 4;          // 0..199
        int c4 = idx & 15;
        const float* src = (rr < RC_) ? (resin + (rr << 15))
                                      : (condb + ((rr - RC_) << 15));
        float4 v = *(const float4*)(src + t0 + c4 * 4);
        *(float4*)(xs + ((120 + rr) << 6) + c4 * 4) = v;
    }
    // rows 0..119 (shifted): scalar with boundary
    for (int idx = tid; idx < RC_ * TT_; idx += NTHR) {
        int r = idx >> 6;
        int t = idx & 63;
        int tt = t0 + t - d;
        xs[(r << 6) + t] = (tt >= 0) ? resin[(r << 15) + tt] : 0.0f;
    }

    const int og = tid >> 4;       // 0..31 (30 active)
    const int tg = tid & 15;       // 4 t each
    const bool active = (og < 30);

    // ---- GEMM1: thread owns outputs {og*4..+3} and {og*4+120..+123} ----
    unsigned long long acc[4][4];
    if (active) {
#pragma unroll
        for (int p = 0; p < 4; p++) {
            int o = og * 4 + (p & 1) * 2 + (p >> 1) * RC_;
            float b0 = dil_b[blk * C2_ + o]     + cond_b[blk * C2_ + o];
            float b1 = dil_b[blk * C2_ + o + 1] + cond_b[blk * C2_ + o + 1];
            unsigned long long bv = pack2(b0, b1);
#pragma unroll
            for (int j = 0; j < 4; j++) acc[p][j] = bv;
        }
    }

    // pipeline: 8 chunks of 40 K-rows, 3 buffers, 1 sync/chunk
#pragma unroll 1
    for (int ch = 0; ch < 8; ch++) {
        if (ch == 7) cp_wait<0>(); else cp_wait<1>();
        __syncthreads();
        if (ch + 2 < 8) {
            const float* src = w1base + (ch + 2) * WCHUNK;
            uint32_t dst = smb + (WB_F + ((ch + 2) % 3) * WCHUNK) * 4;
            for (int i = tid; i < WCHUNK / 4; i += NTHR)
                cp16(dst + i * 16, src + i * 4);
            cp_commit();
        }
        if (active) {
            const float* wb = sm + WB_F + (ch % 3) * WCHUNK;
            const float* xrow = xs + ((ch * 40) << 6) + (tg << 2);
#pragma unroll 5
            for (int cc = 0; cc < 40; cc++) {
                float4 xv = *(const float4*)(xrow + (cc << 6));
                unsigned long long xx0 = pack2(xv.x, xv.x);
                unsigned long long xx1 = pack2(xv.y, xv.y);
                unsigned long long xx2 = pack2(xv.z, xv.z);
                unsigned long long xx3 = pack2(xv.w, xv.w);
                ulonglong2 wA = *(const ulonglong2*)(wb + cc * C2_ + (og << 2));
                ulonglong2 wB = *(const ulonglong2*)(wb + cc * C2_ + RC_ + (og << 2));
                fma2(acc[0][0], wA.x, xx0); fma2(acc[0][1], wA.x, xx1);
                fma2(acc[0][2], wA.x, xx2); fma2(acc[0][3], wA.x, xx3);
                fma2(acc[1][0], wA.y, xx0); fma2(acc[1][1], wA.y, xx1);
                fma2(acc[1][2], wA.y, xx2); fma2(acc[1][3], wA.y, xx3);
                fma2(acc[2][0], wB.x, xx0); fma2(acc[2][1], wB.x, xx1);
                fma2(acc[2][2], wB.x, xx2); fma2(acc[2][3], wB.x, xx3);
                fma2(acc[3][0], wB.y, xx0); fma2(acc[3][1], wB.y, xx1);
                fma2(acc[3][2], wB.y, xx2); fma2(acc[3][3], wB.y, xx3);
            }
        }
    }
    __syncthreads();   // xs + all weight buffers now dead

    // ---- prefetch ALL of W2 (overlaps activation compute) ----
    {
        const float* src = g_w2 + blk * RC_ * O2_;
        uint32_t dst = smb + W2_F * 4;
        for (int i = tid; i < RC_ * O2_ / 4; i += NTHR)
            cp16(dst + i * 16, src + i * 4);
        cp_commit();
    }

    // ---- gated activation entirely in registers ----
    float* act = sm + ACT_F;
    if (active) {
        float a0[4], a1[4], a2[4], a3[4];
#pragma unroll
        for (int j = 0; j < 4; j++) {
            float2 gA = unpack2(acc[0][j]);
            float2 gB = unpack2(acc[1][j]);
            float2 sA = unpack2(acc[2][j]);
            float2 sB = unpack2(acc[3][j]);
            a0[j] = fast_tanh(gA.x) * fast_sig(sA.x);
            a1[j] = fast_tanh(gA.y) * fast_sig(sA.y);
            a2[j] = fast_tanh(gB.x) * fast_sig(sB.x);
            a3[j] = fast_tanh(gB.y) * fast_sig(sB.y);
        }
        int r0 = og * 4;
        *(float4*)(act + ((r0 + 0) << 6) + (tg << 2)) = make_float4(a0[0], a0[1], a0[2], a0[3]);
        *(float4*)(act + ((r0 + 1) << 6) + (tg << 2)) = make_float4(a1[0], a1[1], a1[2], a1[3]);
        *(float4*)(act + ((r0 + 2) << 6) + (tg << 2)) = make_float4(a2[0], a2[1], a2[2], a2[3]);
        *(float4*)(act + ((r0 + 3) << 6) + (tg << 2)) = make_float4(a3[0], a3[1], a3[2], a3[3]);
    }
    cp_wait<0>();
    __syncthreads();   // act + W2 visible

    // ---- GEMM2: 360 outs x 64 t, K=120, W2 fully resident ----
    unsigned long long acc2[6][4];
    if (active) {
#pragma unroll
        for (int q = 0; q < 6; q++) {
            int o = og * 12 + q * 2;
            float b0 = (o < SC_)     ? skip_b[blk * SC_ + o]     : res_b[blk * RC_ + o - SC_];
            float b1 = (o + 1 < SC_) ? skip_b[blk * SC_ + o + 1] : res_b[blk * RC_ + o + 1 - SC_];
            unsigned long long bv = pack2(b0, b1);
#pragma unroll
            for (int j = 0; j < 4; j++) acc2[q][j] = bv;
        }
        const float* w2 = sm + W2_F;
        const float* arow = act + (tg << 2);
#pragma unroll 4
        for (int cc = 0; cc < RC_; cc++) {
            float4 xv = *(const float4*)(arow + (cc << 6));
            unsigned long long xx0 = pack2(xv.x, xv.x);
            unsigned long long xx1 = pack2(xv.y, xv.y);
            unsigned long long xx2 = pack2(xv.z, xv.z);
            unsigned long long xx3 = pack2(xv.w, xv.w);
            const ulonglong2* wrow = (const ulonglong2*)(w2 + cc * O2_ + og * 12);
            ulonglong2 wA = wrow[0];
            ulonglong2 wB = wrow[1];
            ulonglong2 wC = wrow[2];
            fma2(acc2[0][0], wA.x, xx0); fma2(acc2[0][1], wA.x, xx1);
            fma2(acc2[0][2], wA.x, xx2); fma2(acc2[0][3], wA.x, xx3);
            fma2(acc2[1][0], wA.y, xx0); fma2(acc2[1][1], wA.y, xx1);
            fma2(acc2[1][2], wA.y, xx2); fma2(acc2[1][3], wA.y, xx3);
            fma2(acc2[2][0], wB.x, xx0); fma2(acc2[2][1], wB.x, xx1);
            fma2(acc2[2][2], wB.x, xx2); fma2(acc2[2][3], wB.x, xx3);
            fma2(acc2[3][0], wB.y, xx0); fma2(acc2[3][1], wB.y, xx1);
            fma2(acc2[3][2], wB.y, xx2); fma2(acc2[3][3], wB.y, xx3);
            fma2(acc2[4][0], wC.x, xx0); fma2(acc2[4][1], wC.x, xx1);
            fma2(acc2[4][2], wC.x, xx2); fma2(acc2[4][3], wC.x, xx3);
            fma2(acc2[5][0], wC.y, xx0); fma2(acc2[5][1], wC.y, xx1);
            fma2(acc2[5][2], wC.y, xx2); fma2(acc2[5][3], wC.y, xx3);
        }

        // ---- epilogue ----
        const int t = t0 + (tg << 2);
        float* skipb = g_skip + b * SC_ * T_LEN;
#pragma unroll
        for (int q = 0; q < 6; q++) {
            float2 v0 = unpack2(acc2[q][0]);
            float2 v1 = unpack2(acc2[q][1]);
            float2 v2 = unpack2(acc2[q][2]);
            float2 v3 = unpack2(acc2[q][3]);
            int o = og * 12 + q * 2;
            if (o < SC_) {
                float4* p0 = (float4*)(skipb + (o << 15) + t);
                float4* p1 = (float4*)(skipb + ((o + 1) << 15) + t);
                float4 c0 = *p0, c1 = *p1;
                c0.x += v0.x; c0.y += v1.x; c0.z += v2.x; c0.w += v3.x;
                c1.x += v0.y; c1.y += v1.y; c1.z += v2.y; c1.w += v3.y;
                *p0 = c0; *p1 = c1;
            } else {
                int r = o - SC_;
                float4 r0 = *(const float4*)(resin + (r << 15) + t);
                float4 r1 = *(const float4*)(resin + ((r + 1) << 15) + t);
                r0.x += v0.x; r0.y += v1.x; r0.z += v2.x; r0.w += v3.x;
                r1.x += v0.y; r1.y += v1.y; r1.z += v2.y; r1.w += v3.y;
                *(float4*)(resout + (r << 15) + t) = r0;
                *(float4*)(resout + ((r + 1) << 15) + t) = r1;
            }
        }
    }
}

// ---------------------------------------------------------------------------
// Head. SMEM (floats):
//   xsF  [0, 15360)          : relu(skip) 240 x 64            (phase A)
//   a_k  [15360 + k*12288)   : 3 bufs, 48x256 w3 chunks       (phase A)
//   oact [0, 16384)          : relu(o) 256 x 64               (phase B)
//   c_k  [16384 + k*16384)   : 2 bufs, 64x256 w4 chunks       (phase B)
// total 52224 floats = 208896 B
// ---------------------------------------------------------------------------
#define XSF_F   0
#define AB_F    15360
#define ACH     12288       // 48 rows * 256
#define OACT_F  0
#define CB_F    16384
#define CCH     16384       // 64 rows * 256

__global__ __launch_bounds__(NTHR, 1) void final_kernel(
    float* __restrict__ out,
    const float* __restrict__ out_b,
    const float* __restrict__ end_b) {
    extern __shared__ float sm[];
    const uint32_t smb = (uint32_t)__cvta_generic_to_shared(sm);

    const int tid = threadIdx.x;
    const int b   = blockIdx.y;
    const int t0  = blockIdx.x * TT_;

    // prologue: w3 chunks 0,1
#pragma unroll 1
    for (int ch = 0; ch < 2; ch++) {
        const float* src = g_w3 + ch * ACH;
        uint32_t dst = smb + (AB_F + ch * ACH) * 4;
        for (int i = tid; i < ACH / 4; i += NTHR)
            cp16(dst + i * 16, src + i * 4);
        cp_commit();
    }

    // stage relu(skip)
    float* xs = sm + XSF_F;
    const float* skipb = g_skip + b * SC_ * T_LEN;
    for (int idx = tid; idx < SC_ * 16; idx += NTHR) {
        int r = idx >> 4;
        int c4 = idx & 15;
        float4 v = *(const float4*)(skipb + (r << 15) + t0 + c4 * 4);
        v.x = fmaxf(v.x, 0.f); v.y = fmaxf(v.y, 0.f);
        v.z = fmaxf(v.z, 0.f); v.w = fmaxf(v.w, 0.f);
        *(float4*)(xs + (r << 6) + c4 * 4) = v;
    }

    const int og = tid >> 4;    // 0..31
    const int tg = tid & 15;

    // ---- GEMM A: 256 outs, K=240, 5 chunks of 48, 3 buffers ----
    unsigned long long acc[4][4];
#pragma unroll
    for (int p = 0; p < 4; p++) {
        int o = og * 8 + p * 2;
        unsigned long long bv = pack2(out_b[o], out_b[o + 1]);
#pragma unroll
        for (int j = 0; j < 4; j++) acc[p][j] = bv;
    }
#pragma unroll 1
    for (int ch = 0; ch < 5; ch++) {
        if (ch == 4) cp_wait<0>(); else cp_wait<1>();
        __syncthreads();
        if (ch + 2 < 5) {
            const float* src = g_w3 + (ch + 2) * ACH;
            uint32_t dst = smb + (AB_F + ((ch + 2) % 3) * ACH) * 4;
            for (int i = tid; i < ACH / 4; i += NTHR)
                cp16(dst + i * 16, src + i * 4);
            cp_commit();
        }
        const float* wb = sm + AB_F + (ch % 3) * ACH;
        const float* xrow = xs + ((ch * 48) << 6) + (tg << 2);
#pragma unroll 4
        for (int cc = 0; cc < 48; cc++) {
            float4 xv = *(const float4*)(xrow + (cc << 6));
            unsigned long long xx0 = pack2(xv.x, xv.x);
            unsigned long long xx1 = pack2(xv.y, xv.y);
            unsigned long long xx2 = pack2(xv.z, xv.z);
            unsigned long long xx3 = pack2(xv.w, xv.w);
            const ulonglong2* wrow = (const ulonglong2*)(wb + cc * NC_ + og * 8);
            ulonglong2 wA = wrow[0];
            ulonglong2 wB = wrow[1];
            fma2(acc[0][0], wA.x, xx0); fma2(acc[0][1], wA.x, xx1);
            fma2(acc[0][2], wA.x, xx2); fma2(acc[0][3], wA.x, xx3);
            fma2(acc[1][0], wA.y, xx0); fma2(acc[1][1], wA.y, xx1);
            fma2(acc[1][2], wA.y, xx2); fma2(acc[1][3], wA.y, xx3);
            fma2(acc[2][0], wB.x, xx0); fma2(acc[2][1], wB.x, xx1);
            fma2(acc[2][2], wB.x, xx2); fma2(acc[2][3], wB.x, xx3);
            fma2(acc[3][0], wB.y, xx0); fma2(acc[3][1], wB.y, xx1);
            fma2(acc[3][2], wB.y, xx2); fma2(acc[3][3], wB.y, xx3);
        }
    }
    __syncthreads();    // xs + a-buffers dead

    // prefetch w4 chunks 0,1 (overlaps relu/oact writes)
#pragma unroll 1
    for (int ch = 0; ch < 2; ch++) {
        const float* src = g_w4 + ch * CCH;
        uint32_t dst = smb + (CB_F + ch * CCH) * 4;
        for (int i = tid; i < CCH / 4; i += NTHR)
            cp16(dst + i * 16, src + i * 4);
        cp_commit();
    }

    // relu -> oact
    float* oact = sm + OACT_F;
#pragma unroll
    for (int p = 0; p < 4; p++) {
        float2 v0 = unpack2(acc[p][0]);
        float2 v1 = unpack2(acc[p][1]);
        float2 v2 = unpack2(acc[p][2]);
        float2 v3 = unpack2(acc[p][3]);
        int o = og * 8 + p * 2;
        *(float4*)(oact + (o << 6) + (tg << 2)) =
            make_float4(fmaxf(v0.x, 0.f), fmaxf(v1.x, 0.f), fmaxf(v2.x, 0.f), fmaxf(v3.x, 0.f));
        *(float4*)(oact + ((o + 1) << 6) + (tg << 2)) =
            make_float4(fmaxf(v0.y, 0.f), fmaxf(v1.y, 0.f), fmaxf(v2.y, 0.f), fmaxf(v3.y, 0.f));
    }

    // ---- GEMM B: 256 outs, K=256, 4 chunks of 64, 2 buffers ----
    unsigned long long acc2[4][4];
#pragma unroll
    for (int p = 0; p < 4; p++) {
        int o = og * 8 + p * 2;
        unsigned long long bv = pack2(end_b[o], end_b[o + 1]);
#pragma unroll
        for (int j = 0; j < 4; j++) acc2[p][j] = bv;
    }
#pragma unroll 1
    for (int ch = 0; ch < 4; ch++) {
        if (ch == 3) cp_wait<0>(); else cp_wait<1>();
        __syncthreads();        // chunk data + (iter0) oact visible
        const float* wb = sm + CB_F + (ch % 2) * CCH;
        const float* xrow = oact + ((ch * 64) << 6) + (tg << 2);
#pragma unroll 4
        for (int cc = 0; cc < 64; cc++) {
            float4 xv = *(const float4*)(xrow + (cc << 6));
            unsigned long long xx0 = pack2(xv.x, xv.x);
            unsigned long long xx1 = pack2(xv.y, xv.y);
            unsigned long long xx2 = pack2(xv.z, xv.z);
            unsigned long long xx3 = pack2(xv.w, xv.w);
            const ulonglong2* wrow = (const ulonglong2*)(wb + cc * NC_ + og * 8);
            ulonglong2 wA = wrow[0];
            ulonglong2 wB = wrow[1];
            fma2(acc2[0][0], wA.x, xx0); fma2(acc2[0][1], wA.x, xx1);
            fma2(acc2[0][2], wA.x, xx2); fma2(acc2[0][3], wA.x, xx3);
            fma2(acc2[1][0], wA.y, xx0); fma2(acc2[1][1], wA.y, xx1);
            fma2(acc2[1][2], wA.y, xx2); fma2(acc2[1][3], wA.y, xx3);
            fma2(acc2[2][0], wB.x, xx0); fma2(acc2[2][1], wB.x, xx1);
            fma2(acc2[2][2], wB.x, xx2); fma2(acc2[2][3], wB.x, xx3);
            fma2(acc2[3][0], wB.y, xx0); fma2(acc2[3][1], wB.y, xx1);
            fma2(acc2[3][2], wB.y, xx2); fma2(acc2[3][3], wB.y, xx3);
        }
        __syncthreads();        // done reading buf ch%2
        if (ch + 2 < 4) {
            const float* src = g_w4 + (ch + 2) * CCH;
            uint32_t dst = smb + (CB_F + (ch % 2) * CCH) * 4;
            for (int i = tid; i < CCH / 4; i += NTHR)
                cp16(dst + i * 16, src + i * 4);
            cp_commit();
        }
    }

    // write end
    float* outb = out + b * NC_ * T_LEN;
    const int t = t0 + (tg << 2);
#pragma unroll
    for (int p = 0; p < 4; p++) {
        float2 v0 = unpack2(acc2[p][0]);
        float2 v1 = unpack2(acc2[p][1]);
        float2 v2 = unpack2(acc2[p][2]);
        float2 v3 = unpack2(acc2[p][3]);
        int o = og * 8 + p * 2;
        *(float4*)(outb + (o << 15) + t) = make_float4(v0.x, v1.x, v2.x, v3.x);
        *(float4*)(outb + ((o + 1) << 15) + t) = make_float4(v0.y, v1.y, v2.y, v3.y);
    }
}

// ---------------------------------------------------------------------------
extern "C" void kernel_launch(void* const* d_in, const int* in_sizes, int n_in,
                              void* d_out, int out_size) {
    const float* wav    = (const float*)d_in[0];
    const float* cond   = (const float*)d_in[1];
    const float* wav_w  = (const float*)d_in[2];
    const float* wav_b  = (const float*)d_in[3];
    const float* cond_w = (const float*)d_in[4];
    const float* cond_b = (const float*)d_in[5];
    const float* dil_w  = (const float*)d_in[6];
    const float* dil_b  = (const float*)d_in[7];
    const float* skip_w = (const float*)d_in[8];
    const float* skip_b = (const float*)d_in[9];
    const float* res_w  = (const float*)d_in[10];
    const float* res_b  = (const float*)d_in[11];
    const float* out_w  = (const float*)d_in[12];
    const float* out_b  = (const float*)d_in[13];
    const float* end_w  = (const float*)d_in[14];
    const float* end_b  = (const float*)d_in[15];
    float* out = (float*)d_out;

    const int SMEM_BLK = 50880 * (int)sizeof(float);   // 203520
    const int SMEM_FIN = 52224 * (int)sizeof(float);   // 208896
    cudaFuncSetAttribute(block_kernel, cudaFuncAttributeMaxDynamicSharedMemorySize, SMEM_BLK);
    cudaFuncSetAttribute(final_kernel, cudaFuncAttributeMaxDynamicSharedMemorySize, SMEM_FIN);

    prep_kernel<<<512, 256>>>(cond_w, dil_w, skip_w, res_w, out_w, end_w);
    init_kernel<<<592, 256>>>(wav, wav_w, wav_b);

    dim3 grid(T_LEN / TT_, BN);
    for (int i = 0; i < NB_; i++) {
        int d = 1 << (i & 7);
        block_kernel<<<grid, NTHR, SMEM_BLK>>>(i, d, i & 1, cond,
                                               dil_b, cond_b, skip_b, res_b);
    }
    final_kernel<<<grid, NTHR, SMEM_FIN>>>(out, out_b, end_b);
}